// round 1
// baseline (speedup 1.0000x reference)
#include <cuda_runtime.h>
#include <cstdint>

// Problem dims (fixed by the reference)
#define NE 8
#define NC 4096
#define NM 1024
#define NH 4096
#define NO 1024

// Intermediate activations y = relu(x @ w1 + b1): [E, C, H] fp32 = 512 MiB
__device__ float g_y[(size_t)NE * NC * NH];

// Classic 128x128x8 register-tiled SGEMM with fused bias (+ optional ReLU).
// A: [E, Mr, K] row-major, B: [E, K, N] row-major, bias: [E, N], C: [E, Mr, N].
// 256 threads, each computes an 8x8 tile. All dims assumed divisible (they are).
template <bool RELU>
__global__ __launch_bounds__(256, 2)
void sgemm_bias_kernel(const float* __restrict__ A,
                       const float* __restrict__ B,
                       const float* __restrict__ bias,
                       float* __restrict__ C,
                       int Mr, int N, int K)
{
    constexpr int BM = 128, BN = 128, BK = 8, TM = 8, TN = 8;

    __shared__ float As[BK][BM];   // A tile stored transposed for coalesced compute reads
    __shared__ float Bs[BK][BN];

    const int e = blockIdx.z;
    A    += (size_t)e * Mr * K;
    B    += (size_t)e * K  * N;
    bias += (size_t)e * N;
    C    += (size_t)e * Mr * N;

    const int bm = blockIdx.y * BM;
    const int bn = blockIdx.x * BN;

    const int tid = threadIdx.x;
    const int tx  = tid % 16;      // N direction (16 x 8 = 128)
    const int ty  = tid / 16;      // M direction (16 x 8 = 128)

    // Global-load mapping (one float4 per thread per tile per operand)
    const int a_row  = tid >> 1;          // 0..127
    const int a_col  = (tid & 1) * 4;     // 0 or 4
    const int b_row  = tid >> 5;          // 0..7
    const int b_col  = (tid & 31) * 4;    // 0..124

    const float* a_ptr = A + (size_t)(bm + a_row) * K + a_col;
    const float* b_ptr = B + (size_t)b_row * N + bn + b_col;

    float acc[TM][TN] = {};
    float ar[TM], br[TN];

    for (int k0 = 0; k0 < K; k0 += BK) {
        const float4 av = *reinterpret_cast<const float4*>(a_ptr + k0);
        const float4 bv = *reinterpret_cast<const float4*>(b_ptr + (size_t)k0 * N);

        __syncthreads();   // previous iteration's compute must finish before overwrite
        As[a_col + 0][a_row] = av.x;
        As[a_col + 1][a_row] = av.y;
        As[a_col + 2][a_row] = av.z;
        As[a_col + 3][a_row] = av.w;
        *reinterpret_cast<float4*>(&Bs[b_row][b_col]) = bv;
        __syncthreads();

        #pragma unroll
        for (int k = 0; k < BK; k++) {
            #pragma unroll
            for (int i = 0; i < TM; i++) ar[i] = As[k][ty * TM + i];
            #pragma unroll
            for (int j = 0; j < TN; j++) br[j] = Bs[k][tx * TN + j];
            #pragma unroll
            for (int i = 0; i < TM; i++)
                #pragma unroll
                for (int j = 0; j < TN; j++)
                    acc[i][j] = fmaf(ar[i], br[j], acc[i][j]);
        }
    }

    // Epilogue: bias (+ ReLU), float4 stores
    #pragma unroll
    for (int i = 0; i < TM; i++) {
        const int row = bm + ty * TM + i;
        #pragma unroll
        for (int j = 0; j < TN; j += 4) {
            const int col = bn + tx * TN + j;
            float4 v;
            v.x = acc[i][j + 0] + bias[col + 0];
            v.y = acc[i][j + 1] + bias[col + 1];
            v.z = acc[i][j + 2] + bias[col + 2];
            v.w = acc[i][j + 3] + bias[col + 3];
            if (RELU) {
                v.x = fmaxf(v.x, 0.0f);
                v.y = fmaxf(v.y, 0.0f);
                v.z = fmaxf(v.z, 0.0f);
                v.w = fmaxf(v.w, 0.0f);
            }
            *reinterpret_cast<float4*>(&C[(size_t)row * N + col]) = v;
        }
    }
}

extern "C" void kernel_launch(void* const* d_in, const int* in_sizes, int n_in,
                              void* d_out, int out_size)
{
    const float* x   = (const float*)d_in[0];   // [E, C, M]
    const float* w1  = (const float*)d_in[1];   // [E, M, H]
    const float* b1  = (const float*)d_in[2];   // [E, H]
    const float* w2  = (const float*)d_in[3];   // [E, H, O]
    const float* b2  = (const float*)d_in[4];   // [E, O]
    float* out = (float*)d_out;                 // [E, C, O]

    float* y = nullptr;
    cudaGetSymbolAddress((void**)&y, g_y);      // host-side query, not a stream op: capture-safe

    dim3 block(256);

    // fc1: [C, M] @ [M, H] + b1, ReLU  -> y
    dim3 g1(NH / 128, NC / 128, NE);
    sgemm_bias_kernel<true><<<g1, block>>>(x, w1, b1, y, NC, NH, NM);

    // fc2: [C, H] @ [H, O] + b2 -> out
    dim3 g2(NO / 128, NC / 128, NE);
    sgemm_bias_kernel<false><<<g2, block>>>(y, w2, b2, out, NC, NO, NH);
}

// round 2
// speedup vs baseline: 1.0002x; 1.0002x over previous
#include <cuda_runtime.h>
#include <cstdint>

// Problem dims (fixed by the reference)
#define NE 8
#define NC 4096
#define NM 1024
#define NH 4096
#define NO 1024

// Intermediate activations y = relu(x @ w1 + b1): [E, C, H] fp32 = 512 MiB
__device__ float g_y[(size_t)NE * NC * NH];

// Classic 128x128x8 register-tiled SGEMM with fused bias (+ optional ReLU).
// A: [E, Mr, K] row-major, B: [E, K, N] row-major, bias: [E, N], C: [E, Mr, N].
// 256 threads, each computes an 8x8 tile. All dims assumed divisible (they are).
template <bool RELU>
__global__ __launch_bounds__(256, 2)
void sgemm_bias_kernel(const float* __restrict__ A,
                       const float* __restrict__ B,
                       const float* __restrict__ bias,
                       float* __restrict__ C,
                       int Mr, int N, int K)
{
    constexpr int BM = 128, BN = 128, BK = 8, TM = 8, TN = 8;

    __shared__ float As[BK][BM];   // A tile stored transposed for coalesced compute reads
    __shared__ float Bs[BK][BN];

    const int e = blockIdx.z;
    A    += (size_t)e * Mr * K;
    B    += (size_t)e * K  * N;
    bias += (size_t)e * N;
    C    += (size_t)e * Mr * N;

    const int bm = blockIdx.y * BM;
    const int bn = blockIdx.x * BN;

    const int tid = threadIdx.x;
    const int tx  = tid % 16;      // N direction (16 x 8 = 128)
    const int ty  = tid / 16;      // M direction (16 x 8 = 128)

    // Global-load mapping (one float4 per thread per tile per operand)
    const int a_row  = tid >> 1;          // 0..127
    const int a_col  = (tid & 1) * 4;     // 0 or 4
    const int b_row  = tid >> 5;          // 0..7
    const int b_col  = (tid & 31) * 4;    // 0..124

    const float* a_ptr = A + (size_t)(bm + a_row) * K + a_col;
    const float* b_ptr = B + (size_t)b_row * N + bn + b_col;

    float acc[TM][TN] = {};
    float ar[TM], br[TN];

    for (int k0 = 0; k0 < K; k0 += BK) {
        const float4 av = *reinterpret_cast<const float4*>(a_ptr + k0);
        const float4 bv = *reinterpret_cast<const float4*>(b_ptr + (size_t)k0 * N);

        __syncthreads();   // previous iteration's compute must finish before overwrite
        As[a_col + 0][a_row] = av.x;
        As[a_col + 1][a_row] = av.y;
        As[a_col + 2][a_row] = av.z;
        As[a_col + 3][a_row] = av.w;
        *reinterpret_cast<float4*>(&Bs[b_row][b_col]) = bv;
        __syncthreads();

        #pragma unroll
        for (int k = 0; k < BK; k++) {
            #pragma unroll
            for (int i = 0; i < TM; i++) ar[i] = As[k][ty * TM + i];
            #pragma unroll
            for (int j = 0; j < TN; j++) br[j] = Bs[k][tx * TN + j];
            #pragma unroll
            for (int i = 0; i < TM; i++)
                #pragma unroll
                for (int j = 0; j < TN; j++)
                    acc[i][j] = fmaf(ar[i], br[j], acc[i][j]);
        }
    }

    // Epilogue: bias (+ ReLU), float4 stores
    #pragma unroll
    for (int i = 0; i < TM; i++) {
        const int row = bm + ty * TM + i;
        #pragma unroll
        for (int j = 0; j < TN; j += 4) {
            const int col = bn + tx * TN + j;
            float4 v;
            v.x = acc[i][j + 0] + bias[col + 0];
            v.y = acc[i][j + 1] + bias[col + 1];
            v.z = acc[i][j + 2] + bias[col + 2];
            v.w = acc[i][j + 3] + bias[col + 3];
            if (RELU) {
                v.x = fmaxf(v.x, 0.0f);
                v.y = fmaxf(v.y, 0.0f);
                v.z = fmaxf(v.z, 0.0f);
                v.w = fmaxf(v.w, 0.0f);
            }
            *reinterpret_cast<float4*>(&C[(size_t)row * N + col]) = v;
        }
    }
}

extern "C" void kernel_launch(void* const* d_in, const int* in_sizes, int n_in,
                              void* d_out, int out_size)
{
    const float* x   = (const float*)d_in[0];   // [E, C, M]
    const float* w1  = (const float*)d_in[1];   // [E, M, H]
    const float* b1  = (const float*)d_in[2];   // [E, H]
    const float* w2  = (const float*)d_in[3];   // [E, H, O]
    const float* b2  = (const float*)d_in[4];   // [E, O]
    float* out = (float*)d_out;                 // [E, C, O]

    float* y = nullptr;
    cudaGetSymbolAddress((void**)&y, g_y);      // host-side query, not a stream op: capture-safe

    dim3 block(256);

    // fc1: [C, M] @ [M, H] + b1, ReLU  -> y
    dim3 g1(NH / 128, NC / 128, NE);
    sgemm_bias_kernel<true><<<g1, block>>>(x, w1, b1, y, NC, NH, NM);

    // fc2: [C, H] @ [H, O] + b2 -> out
    dim3 g2(NO / 128, NC / 128, NE);
    sgemm_bias_kernel<false><<<g2, block>>>(y, w2, b2, out, NC, NO, NH);
}